// round 12
// baseline (speedup 1.0000x reference)
#include <cuda_runtime.h>
#include <cuda_bf16.h>

#define TPB   256
#define ROWS  64          // batch rows per CTA
#define HSTRB 144         // bytes per H row (72 bf16): (4*gid+tg)%32 conflict-free

typedef unsigned int u32;

// ---------- helpers ----------
__device__ __forceinline__ unsigned short f2bf(float f) {
    unsigned short u; asm("cvt.rn.bf16.f32 %0, %1;" : "=h"(u) : "f"(f)); return u;
}
__device__ __forceinline__ float bf2f(unsigned short u) { return __uint_as_float((u32)u << 16); }
__device__ __forceinline__ u32 packbf(unsigned short lo, unsigned short hi) {
    return (u32)lo | ((u32)hi << 16);
}
__device__ __forceinline__ float tanh_hw(float x) {
    float y; asm("tanh.approx.f32 %0, %1;" : "=f"(y) : "f"(x)); return y;
}
__device__ __forceinline__ float sigm(float x) {   // sigma(x) = 0.5 + 0.5*tanh(x/2)
    return fmaf(0.5f, tanh_hw(0.5f * x), 0.5f);
}
// m16n8k16 bf16 MMA, f32 accum (HMMA path on sm_103)
__device__ __forceinline__ void mma16816(float* d, u32 a0, u32 a1, u32 a2, u32 a3,
                                         u32 b0, u32 b1) {
    asm volatile("mma.sync.aligned.m16n8k16.row.col.f32.bf16.bf16.f32 "
                 "{%0,%1,%2,%3}, {%4,%5,%6,%7}, {%8,%9}, {%0,%1,%2,%3};"
                 : "+f"(d[0]), "+f"(d[1]), "+f"(d[2]), "+f"(d[3])
                 : "r"(a0), "r"(a1), "r"(a2), "r"(a3), "r"(b0), "r"(b1));
}

// SMEM byte offsets
#define OFF_UF   0                       // frag-linear U (hi+lo): 32N x 4kt x 32 lanes x 16B = 65536
#define OFF_HH0  65536                   // H hi, buf0: 64 x 144 = 9216
#define OFF_HL0  (OFF_HH0 +  9216)       // H lo, buf0
#define OFF_HH1  (OFF_HH0 + 18432)       // H hi, buf1
#define OFF_HL1  (OFF_HH0 + 27648)       // H lo, buf1
#define OFF_SW   (OFF_HH0 + 36864)       // W[256] f32
#define OFF_SB   (OFF_SW + 1024)         // b[256] f32
#define OFF_SWD  (OFF_SB + 1024)         // Wd[64] f32
#define OFF_SX   (OFF_SWD + 256)         // x[64*5] f32
#define SMEM_BYTES (OFF_SX + 1280)       // 105984 B -> 2 CTAs/SM

__global__ void __launch_bounds__(TPB, 2)
lstm_mma(const float* __restrict__ x, const float* __restrict__ W,
         const float* __restrict__ U, const float* __restrict__ b,
         const float* __restrict__ Wd, const float* __restrict__ bd,
         float* __restrict__ out, int Bn)
{
    extern __shared__ char smem[];
    float* sW  = (float*)(smem + OFF_SW);
    float* sB  = (float*)(smem + OFF_SB);
    float* sWd = (float*)(smem + OFF_SWD);
    float* sX  = (float*)(smem + OFF_SX);

    const int tid  = threadIdx.x;
    const int lane = tid & 31;
    const int wid  = tid >> 5;
    const int gid  = lane >> 2;          // frag group id (row / B-col index)
    const int tg   = lane & 3;           // frag thread-in-group (k / D-col index)
    const int rg   = wid >> 2;           // row-group: rows [rg*32, rg*32+32)
    const int cg   = wid & 3;            // unit-group: units [cg*16, cg*16+16)
    const long rowBase = (long)blockIdx.x * ROWS;

    // ---- stage: frag-linear U (hi/lo bf16), W, b, Wd, x ----
    for (int idx = tid; idx < 4096; idx += TPB) {
        const int N  = idx >> 7;         // global n-tile 0..31
        const int kt = (idx >> 5) & 3;   // k-tile 0..3
        const int l  = idx & 31;
        const int g2 = l >> 2, t2 = l & 3;
        const int col = N * 8 + g2;
        const int k0  = kt * 16 + 2 * t2;
        const float u0 = U[k0 * 256 + col],       u1 = U[(k0 + 1) * 256 + col];
        const float u8 = U[(k0 + 8) * 256 + col], u9 = U[(k0 + 9) * 256 + col];
        const unsigned short h0 = f2bf(u0), h1 = f2bf(u1), h8 = f2bf(u8), h9 = f2bf(u9);
        const unsigned short l0 = f2bf(u0 - bf2f(h0)), l1 = f2bf(u1 - bf2f(h1));
        const unsigned short l8 = f2bf(u8 - bf2f(h8)), l9 = f2bf(u9 - bf2f(h9));
        uint4 v;
        v.x = packbf(h0, h1);  v.y = packbf(h8, h9);   // B_hi regs
        v.z = packbf(l0, l1);  v.w = packbf(l8, l9);   // B_lo regs
        *(uint4*)(smem + OFF_UF + idx * 16) = v;
    }
    sW[tid] = W[tid];
    sB[tid] = b[tid];
    if (tid < 64) sWd[tid] = Wd[tid];
    {
        const float* xs = x + rowBase * 5;
        for (int i = tid; i < ROWS * 5; i += TPB)
            if (rowBase * 5 + i < (long)Bn * 5) sX[i] = xs[i];
    }
    __syncthreads();

    float c[16];                         // c-state
#pragma unroll
    for (int i = 0; i < 16; ++i) c[i] = 0.f;
    float pd[4];                         // dense partials
#pragma unroll
    for (int i = 0; i < 4; ++i) pd[i] = 0.f;

#pragma unroll 1
    for (int t = 0; t < 5; ++t) {
        // ---- acc init: z = x*W + b ----
        float acc[2][4][2][4];           // [mi][gate][j][2h+e]
#pragma unroll
        for (int mi = 0; mi < 2; ++mi) {
            const int row0 = rg * 32 + mi * 16 + gid;
            const float xr0 = sX[row0 * 5 + t];
            const float xr1 = sX[(row0 + 8) * 5 + t];
#pragma unroll
            for (int ga = 0; ga < 4; ++ga)
#pragma unroll
                for (int j = 0; j < 2; ++j) {
                    const int colb = ga * 64 + cg * 16 + 8 * j + 2 * tg;
                    const float2 w2 = *(const float2*)(sW + colb);
                    const float2 b2 = *(const float2*)(sB + colb);
                    acc[mi][ga][j][0] = fmaf(xr0, w2.x, b2.x);
                    acc[mi][ga][j][1] = fmaf(xr0, w2.y, b2.y);
                    acc[mi][ga][j][2] = fmaf(xr1, w2.x, b2.x);
                    acc[mi][ga][j][3] = fmaf(xr1, w2.y, b2.y);
                }
        }

        // ---- tensor mainloop (software-pipelined over kt) ----
        if (t > 0) {
            const char* HH = smem + (((t - 1) & 1) ? OFF_HH1 : OFF_HH0);
            const char* HL = smem + (((t - 1) & 1) ? OFF_HL1 : OFF_HL0);
            const int abase = (rg * 32 + gid) * HSTRB + 4 * tg;   // + kt*32 bytes

            u32 ah[2][2][4], al[2][2][4];   // [buf][mi][frag]
#pragma unroll
            for (int mi = 0; mi < 2; ++mi) {   // prologue: load kt=0
                const int off = abase + mi * 16 * HSTRB;
                ah[0][mi][0] = *(const u32*)(HH + off);
                ah[0][mi][1] = *(const u32*)(HH + off + 8 * HSTRB);
                ah[0][mi][2] = *(const u32*)(HH + off + 16);
                ah[0][mi][3] = *(const u32*)(HH + off + 8 * HSTRB + 16);
                al[0][mi][0] = *(const u32*)(HL + off);
                al[0][mi][1] = *(const u32*)(HL + off + 8 * HSTRB);
                al[0][mi][2] = *(const u32*)(HL + off + 16);
                al[0][mi][3] = *(const u32*)(HL + off + 8 * HSTRB + 16);
            }
#pragma unroll
            for (int kt = 0; kt < 4; ++kt) {
                const int cur = kt & 1, nxt = cur ^ 1;
                if (kt < 3) {                 // prefetch kt+1 under this kt's MMAs
#pragma unroll
                    for (int mi = 0; mi < 2; ++mi) {
                        const int off = abase + (kt + 1) * 32 + mi * 16 * HSTRB;
                        ah[nxt][mi][0] = *(const u32*)(HH + off);
                        ah[nxt][mi][1] = *(const u32*)(HH + off + 8 * HSTRB);
                        ah[nxt][mi][2] = *(const u32*)(HH + off + 16);
                        ah[nxt][mi][3] = *(const u32*)(HH + off + 8 * HSTRB + 16);
                        al[nxt][mi][0] = *(const u32*)(HL + off);
                        al[nxt][mi][1] = *(const u32*)(HL + off + 8 * HSTRB);
                        al[nxt][mi][2] = *(const u32*)(HL + off + 16);
                        al[nxt][mi][3] = *(const u32*)(HL + off + 8 * HSTRB + 16);
                    }
                }
#pragma unroll
                for (int ga = 0; ga < 4; ++ga)
#pragma unroll
                    for (int j = 0; j < 2; ++j) {
                        const int N = 8 * ga + 2 * cg + j;
                        const uint4 bf = *(const uint4*)(smem + OFF_UF + ((N * 4 + kt) * 32 + lane) * 16);
#pragma unroll
                        for (int mi = 0; mi < 2; ++mi) {
                            mma16816(acc[mi][ga][j], ah[cur][mi][0], ah[cur][mi][1],
                                     ah[cur][mi][2], ah[cur][mi][3], bf.x, bf.y);
                            mma16816(acc[mi][ga][j], ah[cur][mi][0], ah[cur][mi][1],
                                     ah[cur][mi][2], ah[cur][mi][3], bf.z, bf.w);
                            mma16816(acc[mi][ga][j], al[cur][mi][0], al[cur][mi][1],
                                     al[cur][mi][2], al[cur][mi][3], bf.x, bf.y);
                        }
                    }
            }
        }

        // ---- epilogue: gates -> c,h; h -> bf16 hi/lo into H(t&1) ----
        const bool last = (t == 4);
        char* HHn = smem + ((t & 1) ? OFF_HH1 : OFF_HH0);
        char* HLn = smem + ((t & 1) ? OFF_HL1 : OFF_HL0);

#pragma unroll
        for (int mi = 0; mi < 2; ++mi)
#pragma unroll
            for (int h = 0; h < 2; ++h) {
                const int row = rg * 32 + mi * 16 + gid + 8 * h;
#pragma unroll
                for (int j = 0; j < 2; ++j) {
                    const int ub = cg * 16 + 8 * j + 2 * tg;
                    float hv[2];
#pragma unroll
                    for (int e = 0; e < 2; ++e) {
                        const int ix = 2 * h + e;
                        const float zi = acc[mi][0][j][ix];
                        const float zf = acc[mi][1][j][ix];
                        const float zg = acc[mi][2][j][ix];
                        const float zo = acc[mi][3][j][ix];
                        const float ig = sigm(zi), fg = sigm(zf);
                        const float gg = tanh_hw(zg), og = sigm(zo);
                        const int cid = mi * 8 + h * 4 + j * 2 + e;
                        const float cn = fmaf(fg, c[cid], ig * gg);
                        c[cid] = cn;
                        hv[e] = og * tanh_hw(cn);
                    }
                    if (!last) {
                        const unsigned short h0 = f2bf(hv[0]), h1 = f2bf(hv[1]);
                        const unsigned short l0 = f2bf(hv[0] - bf2f(h0));
                        const unsigned short l1 = f2bf(hv[1] - bf2f(h1));
                        *(u32*)(HHn + row * HSTRB + ub * 2) = packbf(h0, h1);
                        *(u32*)(HLn + row * HSTRB + ub * 2) = packbf(l0, l1);
                    } else {
                        const float2 wd2 = *(const float2*)(sWd + ub);
                        pd[mi * 2 + h] = fmaf(hv[0], wd2.x, fmaf(hv[1], wd2.y, pd[mi * 2 + h]));
                    }
                }
            }

        if (!last) {
            // sync only the 4 warps sharing this row-group's H rows
            asm volatile("bar.sync %0, 128;" :: "r"(rg + 1) : "memory");
        }
    }

    // ---- Dense(1, relu): scratch reduce over 16 (cg,tg) slots per row ----
    float* scr = (float*)(smem + OFF_HH0);      // H buf0 region free at t=4
#pragma unroll
    for (int mi = 0; mi < 2; ++mi)
#pragma unroll
        for (int h = 0; h < 2; ++h) {
            const int row = rg * 32 + mi * 16 + gid + 8 * h;
            scr[row * 16 + cg * 4 + tg] = pd[mi * 2 + h];
        }
    __syncthreads();
    if (tid < ROWS) {
        float s = 0.f;
#pragma unroll
        for (int k = 0; k < 16; ++k) s += scr[tid * 16 + k];
        const long orow = rowBase + tid;
        if (orow < Bn) out[orow] = fmaxf(s + __ldg(bd), 0.f);
    }
}

extern "C" void kernel_launch(void* const* d_in, const int* in_sizes, int n_in,
                              void* d_out, int out_size) {
    const float* x  = (const float*)d_in[0];
    const float* W  = (const float*)d_in[1];
    const float* U  = (const float*)d_in[2];
    const float* b  = (const float*)d_in[3];
    const float* Wd = (const float*)d_in[4];
    const float* bd = (const float*)d_in[5];
    float* out = (float*)d_out;

    const int Bn = in_sizes[0] / 5;      // x is [B, 5, 1]
    cudaFuncSetAttribute(lstm_mma, cudaFuncAttributeMaxDynamicSharedMemorySize, SMEM_BYTES);

    const int grid = (Bn + ROWS - 1) / ROWS;
    lstm_mma<<<grid, TPB, SMEM_BYTES>>>(x, W, U, b, Wd, bd, out, Bn);
}